// round 14
// baseline (speedup 1.0000x reference)
#include <cuda_runtime.h>
#include <cuda_fp16.h>
#include <cstdint>

// ---------------------------------------------------------------------------
// Problem constants
// ---------------------------------------------------------------------------
#define B_   16
#define C_   306
#define CP_  320      // C padded to multiple of 32
#define T_   4000
#define M_   128
#define TN_  64       // t-tile per CTA
#define KC_  32       // K chunk
#define NCHUNK 10     // CP_/KC_
#define NTT  63       // ceil(T_/TN_)

#define INV0 50.0f
#define INV1 12.5f
#define INV2 3.125f

// smem row strides (data + 16B pad -> conflict-free ldmatrix)
#define RS   80       // A rows and B rows (64B fp16 data)
#define RSX  272      // X staging rows (256B fp32 data)

// SMEM layout (bytes, dynamic) — 3 uniform stages for full/empty pipelining
#define OFF_A(s)  ((s) * 10240)            // 3 stages: 128 rows x 80
#define OFF_X(s)  (30720 + (s) * 8704)     // 3 stages: 32 rows x 272
#define OFF_B(s)  (56832 + (s) * 5120)     // 3 stages: 64 rows x 80
#define SMEM_TOTAL 72192

#define NTHREADS 384   // 8 consumer warps + 4 producer warps

// Scratch: normalized channel weights, fp16, layout [b][m][c] (padded)
__device__ __align__(16) __half g_w[B_ * M_ * CP_];

__device__ __forceinline__ uint32_t smem_u32(const void* p) {
    uint32_t a;
    asm("{ .reg .u64 t; cvta.to.shared.u64 t, %1; cvt.u32.u64 %0, t; }" : "=r"(a) : "l"(p));
    return a;
}

#define LDSM4(r, addr) \
    asm volatile("ldmatrix.sync.aligned.m8n8.x4.shared.b16 {%0,%1,%2,%3}, [%4];" \
        : "=r"((r)[0]), "=r"((r)[1]), "=r"((r)[2]), "=r"((r)[3]) : "r"(addr))

#define STS16(addr, v) \
    asm volatile("st.shared.v4.b32 [%0], {%1,%2,%3,%4};" \
        :: "r"(addr), "r"((v).x), "r"((v).y), "r"((v).z), "r"((v).w) : "memory")

#define CP16(dst, src, sz) \
    asm volatile("cp.async.cg.shared.global [%0], [%1], 16, %2;" \
        :: "r"(dst), "l"(src), "r"(sz) : "memory")

#define CP_COMMIT() asm volatile("cp.async.commit_group;" ::: "memory")

// Producer-only barrier (cross-thread cp.async visibility before convert), id 1.
#define PROD_BAR() asm volatile("bar.sync 1, 128;" ::: "memory")

// Named full/empty barriers: full[s] = id 2+s, empty[s] = id 5+s, count 384.
#define BAR_SYNC(id)   asm volatile("bar.sync %0, 384;"   :: "r"(id) : "memory")
#define BAR_ARRIVE(id) asm volatile("bar.arrive %0, 384;" :: "r"(id) : "memory")

#define MMA_F16(c, a, b0, b1) \
    asm volatile("mma.sync.aligned.m16n8k16.row.col.f32.f16.f16.f32 " \
        "{%0,%1,%2,%3}, {%4,%5,%6,%7}, {%8,%9}, {%0,%1,%2,%3};" \
        : "+f"((c)[0]), "+f"((c)[1]), "+f"((c)[2]), "+f"((c)[3]) \
        : "r"((a)[0]), "r"((a)[1]), "r"((a)[2]), "r"((a)[3]), "r"(b0), "r"(b1))

// ---------------------------------------------------------------------------
// Kernel 1: gate weights (R9 form: one (b,m) per block — fastest measured).
// ---------------------------------------------------------------------------
__global__ void __launch_bounds__(CP_) mrm_weights_kernel(
    const float* __restrict__ pos, const float* __restrict__ tpos,
    const float* __restrict__ w1, const float* __restrict__ b1,
    const float* __restrict__ w2, const float* __restrict__ b2)
{
    __shared__ float s_w1[96], s_b1[32], s_w2[32];
    __shared__ float warp_sums[10];
    __shared__ float s_total;

    const int bm = blockIdx.x;
    const int b = bm / M_, m = bm % M_;
    const int tid = threadIdx.x;

    if (tid < 96) s_w1[tid] = w1[tid];
    else if (tid < 128) s_b1[tid - 96] = b1[tid - 96];
    else if (tid < 160) s_w2[tid - 128] = w2[tid - 128];
    __syncthreads();

    const float txp = tpos[2 * m], typ = tpos[2 * m + 1];
    const float bias2 = b2[0];

    float wv = 0.0f;
    const int c = tid;
    if (c < C_) {
        const float px = pos[((size_t)b * C_ + c) * 2 + 0];
        const float py = pos[((size_t)b * C_ + c) * 2 + 1];
        const float dx = px - txp, dy = py - typ;
        const float d2 = dx * dx + dy * dy;
        const float s0 = __expf(-d2 * INV0);
        const float s1 = __expf(-d2 * INV1);
        const float s2 = __expf(-d2 * INV2);
        float acc = bias2;
#pragma unroll
        for (int j = 0; j < 32; j++) {
            float h = s_b1[j];
            h = fmaf(s0, s_w1[j], h);
            h = fmaf(s1, s_w1[32 + j], h);
            h = fmaf(s2, s_w1[64 + j], h);
            h = fmaxf(h, 0.0f);
            acc = fmaf(h, s_w2[j], acc);
        }
        wv = acc;
    }

    float v = wv;
#pragma unroll
    for (int o = 16; o > 0; o >>= 1) v += __shfl_down_sync(0xffffffffu, v, o);
    if ((tid & 31) == 0) warp_sums[tid >> 5] = v;
    __syncthreads();
    if (tid == 0) {
        float s = 0.0f;
#pragma unroll
        for (int i = 0; i < 10; i++) s += warp_sums[i];
        s_total = s + 1e-8f;
    }
    __syncthreads();

    const float wn = (c < C_) ? (wv / s_total) : 0.0f;   // padding rows get 0
    g_w[((size_t)b * M_ + m) * CP_ + c] = __float2half(wn);
}

// ---------------------------------------------------------------------------
// Kernel 2: warp-specialized fp16 HMMA GEMM, CTA tile 128x64,
// decoupled producer/consumer via named full/empty barriers (3 stages).
// ---------------------------------------------------------------------------
__global__ void __launch_bounds__(NTHREADS, 2) mrm_hmma_kernel(
    const float* __restrict__ x, float* __restrict__ out)
{
    extern __shared__ __align__(16) char smem[];
    const uint32_t sb = smem_u32(smem);

    const int b   = blockIdx.y;
    const int t0  = blockIdx.x * TN_;
    const int tid = threadIdx.x;
    const int lane = tid & 31;
    const bool is_producer = (tid >= 256);

    const float* xb = x + (size_t)b * C_ * T_;
    const char* xrow_base = (const char*)(xb) + (size_t)t0 * 4;
    const __half* gw = g_w + (size_t)b * M_ * CP_;

    if (is_producer) {
        // =============== PRODUCERS (4 warps) ===============
        const int ptid = tid - 256;        // 0..127
        const int ph   = ptid >> 6;        // k half 0/1
        const int tcol = ptid & 63;        // t column 0..63

        auto issue_chunk = [&](int chunk) {
            const int k0 = chunk * KC_;
            const int s  = chunk % 3;
#pragma unroll
            for (int r = 0; r < 4; r++) {
                const int c = ptid + r * 128;
                const int row = c >> 2, j = c & 3;
                const __half* src = gw + (size_t)row * CP_ + k0 + j * 8;
                CP16(sb + OFF_A(s) + row * RS + j * 16, src, 16);
            }
#pragma unroll
            for (int r = 0; r < 4; r++) {
                const int c = ptid + r * 128;
                const int k = c >> 4;
                const int j = c & 15;
                const char* src = xrow_base + (size_t)(k0 + k) * (T_ * 4) + j * 16;
                const uint32_t dst = sb + OFF_X(s) + k * RSX + j * 16;
                const uint32_t sz = ((k0 + k) < C_ && (t0 + j * 4) < T_) ? 16u : 0u;
                CP16(dst, src, sz);
            }
            CP_COMMIT();
        };

        auto convert_chunk = [&](int chunk) {
            const int k0 = chunk * KC_;
            const int s  = chunk % 3;
            const uint32_t xbase = sb + OFF_X(s) + ph * (16 * RSX) + tcol * 4;
            float v[16];
#pragma unroll
            for (int j = 0; j < 16; j++) {
                float f;
                asm volatile("ld.shared.f32 %0, [%1];" : "=f"(f) : "r"(xbase + j * RSX));
                v[j] = ((k0 + ph * 16 + j) < C_) ? f : 0.0f;   // kill padding
            }
            uint32_t hp[8];
#pragma unroll
            for (int q = 0; q < 8; q++) {
                __half h0 = __float2half(v[2 * q]);
                __half h1 = __float2half(v[2 * q + 1]);
                hp[q] = (uint32_t)__half_as_ushort(h0)
                      | ((uint32_t)__half_as_ushort(h1) << 16);
            }
            const uint32_t bbase = sb + OFF_B(s) + tcol * RS + ph * 32;
            uint4 v0 = make_uint4(hp[0], hp[1], hp[2], hp[3]);
            uint4 v1 = make_uint4(hp[4], hp[5], hp[6], hp[7]);
            STS16(bbase,      v0);
            STS16(bbase + 16, v1);
        };

        issue_chunk(0);
        for (int j = 0; j < NCHUNK; j++) {
            if (j + 1 < NCHUNK) {
                if (j + 1 >= 3) BAR_SYNC(5 + (j + 1) % 3);   // stage free?
                issue_chunk(j + 1);
                asm volatile("cp.async.wait_group 1;" ::: "memory");
            } else {
                asm volatile("cp.async.wait_group 0;" ::: "memory");
            }
            PROD_BAR();                                      // cross-thread cp.async vis
            convert_chunk(j);
            BAR_ARRIVE(2 + j % 3);                           // stage full
        }
    } else {
        // =============== CONSUMERS (8 warps, 4(m) x 2(n)) ===============
        const int wid = tid >> 5;
        const int warp_m = wid >> 1;        // 0..3
        const int warp_n = wid & 1;         // 0..1

        const int lr  = lane & 7;
        const int sel = lane >> 3;          // 0..3
        const int a_row = warp_m * 32 + lr + (sel & 1) * 8;
        const int a_col = (sel >> 1) * 16;
        const int b_row = warp_n * 32 + lr + (sel >> 1) * 8;
        const int b_col = (sel & 1) * 16;

        float acc[2][4][4];
#pragma unroll
        for (int i = 0; i < 2; i++)
#pragma unroll
            for (int j = 0; j < 4; j++)
#pragma unroll
                for (int q = 0; q < 4; q++) acc[i][j][q] = 0.0f;

        for (int i = 0; i < NCHUNK; i++) {
            const int s = i % 3;
            BAR_SYNC(2 + s);                                 // stage full?
            const uint32_t sA = sb + OFF_A(s);
            const uint32_t sB = sb + OFF_B(s);
#pragma unroll
            for (int ks = 0; ks < 2; ks++) {
                uint32_t af[2][4], bf[2][4];
                const uint32_t acol = ks * 32 + a_col;
                const uint32_t bcol = ks * 32 + b_col;
#pragma unroll
                for (int g = 0; g < 2; g++)
                    LDSM4(bf[g], sB + (uint32_t)(b_row + g * 16) * RS + bcol);
#pragma unroll
                for (int mf = 0; mf < 2; mf++)
                    LDSM4(af[mf], sA + (uint32_t)(a_row + mf * 16) * RS + acol);
#pragma unroll
                for (int mf = 0; mf < 2; mf++)
#pragma unroll
                    for (int nf = 0; nf < 4; nf++) {
                        const int g = nf >> 1, s2 = (nf & 1) * 2;
                        MMA_F16(acc[mf][nf], af[mf], bf[g][s2], bf[g][s2 + 1]);
                    }
            }
            BAR_ARRIVE(5 + s);                               // stage empty
        }

        // epilogue
        if (t0 + warp_n * 32 < T_) {
            const int mb = warp_m * 32 + (lane >> 2);
            const int cb = t0 + warp_n * 32 + (lane & 3) * 2;
#pragma unroll
            for (int mf = 0; mf < 2; mf++) {
#pragma unroll
                for (int nf = 0; nf < 4; nf++) {
                    const int m = mb + mf * 16;
                    const int t = cb + nf * 8;
                    float* o0 = out + ((size_t)b * M_ + m) * T_ + t;
                    float* o1 = out + ((size_t)b * M_ + m + 8) * T_ + t;
                    *(float2*)o0 = make_float2(acc[mf][nf][0], acc[mf][nf][1]);
                    *(float2*)o1 = make_float2(acc[mf][nf][2], acc[mf][nf][3]);
                }
            }
        }
    }
}

// ---------------------------------------------------------------------------
extern "C" void kernel_launch(void* const* d_in, const int* in_sizes, int n_in,
                              void* d_out, int out_size) {
    const float* x    = (const float*)d_in[0];
    const float* pos  = (const float*)d_in[1];
    const float* tpos = (const float*)d_in[2];
    const float* w1   = (const float*)d_in[3];
    const float* b1   = (const float*)d_in[4];
    const float* w2   = (const float*)d_in[5];
    const float* b2   = (const float*)d_in[6];
    float* out = (float*)d_out;

    cudaFuncSetAttribute(mrm_hmma_kernel,
                         cudaFuncAttributeMaxDynamicSharedMemorySize, SMEM_TOTAL);

    mrm_weights_kernel<<<B_ * M_, CP_>>>(pos, tpos, w1, b1, w2, b2);

    dim3 grid(NTT, B_);   // 63 x 16 = 1008 CTAs
    mrm_hmma_kernel<<<grid, NTHREADS, SMEM_TOTAL>>>(x, out);
}

// round 15
// speedup vs baseline: 1.1118x; 1.1118x over previous
#include <cuda_runtime.h>
#include <cuda_fp16.h>
#include <cstdint>

// ---------------------------------------------------------------------------
// Problem constants
// ---------------------------------------------------------------------------
#define B_   16
#define C_   306
#define CP_  320      // C padded to multiple of 32
#define T_   4000
#define M_   128
#define TN_  64       // t-tile per CTA
#define KC_  32       // K chunk
#define NCHUNK 10     // CP_/KC_
#define NTT  63       // ceil(T_/TN_)
#define NSTAGE 4      // pipeline stages (prefetch distance 3)

#define INV0 50.0f
#define INV1 12.5f
#define INV2 3.125f

// smem row strides (data + 16B pad -> conflict-free ldmatrix)
#define RS   80       // A rows and B rows (64B fp16 data)
#define RSX  272      // X staging rows (256B fp32 data)

// SMEM layout (bytes, dynamic) — 4 uniform stages
#define OFF_A(s)  ((s) * 10240)            // 4 stages: 128 rows x 80
#define OFF_X(s)  (40960 + (s) * 8704)     // 4 stages: 32 rows x 272
#define OFF_B(s)  (75776 + (s) * 5120)     // 4 stages: 64 rows x 80
#define SMEM_TOTAL 96256

#define NTHREADS 384   // 8 consumer warps + 4 producer warps

// Scratch: normalized channel weights, fp16, layout [b][m][c] (padded)
__device__ __align__(16) __half g_w[B_ * M_ * CP_];

__device__ __forceinline__ uint32_t smem_u32(const void* p) {
    uint32_t a;
    asm("{ .reg .u64 t; cvta.to.shared.u64 t, %1; cvt.u32.u64 %0, t; }" : "=r"(a) : "l"(p));
    return a;
}

#define LDSM4(r, addr) \
    asm volatile("ldmatrix.sync.aligned.m8n8.x4.shared.b16 {%0,%1,%2,%3}, [%4];" \
        : "=r"((r)[0]), "=r"((r)[1]), "=r"((r)[2]), "=r"((r)[3]) : "r"(addr))

#define STS16(addr, v) \
    asm volatile("st.shared.v4.b32 [%0], {%1,%2,%3,%4};" \
        :: "r"(addr), "r"((v).x), "r"((v).y), "r"((v).z), "r"((v).w) : "memory")

#define CP16(dst, src, sz) \
    asm volatile("cp.async.cg.shared.global [%0], [%1], 16, %2;" \
        :: "r"(dst), "l"(src), "r"(sz) : "memory")

#define CP_COMMIT() asm volatile("cp.async.commit_group;" ::: "memory")

// Producer-only barrier (cross-thread cp.async visibility before convert).
#define PROD_BAR() asm volatile("bar.sync 1, 128;" ::: "memory")

#define MMA_F16(c, a, b0, b1) \
    asm volatile("mma.sync.aligned.m16n8k16.row.col.f32.f16.f16.f32 " \
        "{%0,%1,%2,%3}, {%4,%5,%6,%7}, {%8,%9}, {%0,%1,%2,%3};" \
        : "+f"((c)[0]), "+f"((c)[1]), "+f"((c)[2]), "+f"((c)[3]) \
        : "r"((a)[0]), "r"((a)[1]), "r"((a)[2]), "r"((a)[3]), "r"(b0), "r"(b1))

// ---------------------------------------------------------------------------
// Kernel 1: gate weights (one (b,m) per block — fastest measured form).
// ---------------------------------------------------------------------------
__global__ void __launch_bounds__(CP_) mrm_weights_kernel(
    const float* __restrict__ pos, const float* __restrict__ tpos,
    const float* __restrict__ w1, const float* __restrict__ b1,
    const float* __restrict__ w2, const float* __restrict__ b2)
{
    __shared__ float s_w1[96], s_b1[32], s_w2[32];
    __shared__ float warp_sums[10];
    __shared__ float s_total;

    const int bm = blockIdx.x;
    const int b = bm / M_, m = bm % M_;
    const int tid = threadIdx.x;

    if (tid < 96) s_w1[tid] = w1[tid];
    else if (tid < 128) s_b1[tid - 96] = b1[tid - 96];
    else if (tid < 160) s_w2[tid - 128] = w2[tid - 128];
    __syncthreads();

    const float txp = tpos[2 * m], typ = tpos[2 * m + 1];
    const float bias2 = b2[0];

    float wv = 0.0f;
    const int c = tid;
    if (c < C_) {
        const float px = pos[((size_t)b * C_ + c) * 2 + 0];
        const float py = pos[((size_t)b * C_ + c) * 2 + 1];
        const float dx = px - txp, dy = py - typ;
        const float d2 = dx * dx + dy * dy;
        const float s0 = __expf(-d2 * INV0);
        const float s1 = __expf(-d2 * INV1);
        const float s2 = __expf(-d2 * INV2);
        float acc = bias2;
#pragma unroll
        for (int j = 0; j < 32; j++) {
            float h = s_b1[j];
            h = fmaf(s0, s_w1[j], h);
            h = fmaf(s1, s_w1[32 + j], h);
            h = fmaf(s2, s_w1[64 + j], h);
            h = fmaxf(h, 0.0f);
            acc = fmaf(h, s_w2[j], acc);
        }
        wv = acc;
    }

    float v = wv;
#pragma unroll
    for (int o = 16; o > 0; o >>= 1) v += __shfl_down_sync(0xffffffffu, v, o);
    if ((tid & 31) == 0) warp_sums[tid >> 5] = v;
    __syncthreads();
    if (tid == 0) {
        float s = 0.0f;
#pragma unroll
        for (int i = 0; i < 10; i++) s += warp_sums[i];
        s_total = s + 1e-8f;
    }
    __syncthreads();

    const float wn = (c < C_) ? (wv / s_total) : 0.0f;   // padding rows get 0
    g_w[((size_t)b * M_ + m) * CP_ + c] = __float2half(wn);
}

// ---------------------------------------------------------------------------
// Kernel 2: warp-specialized fp16 HMMA GEMM, CTA tile 128x64, 4-stage
// cp.async pipeline (prefetch distance 3), single lockstep barrier per chunk.
// ---------------------------------------------------------------------------
__global__ void __launch_bounds__(NTHREADS, 2) mrm_hmma_kernel(
    const float* __restrict__ x, float* __restrict__ out)
{
    extern __shared__ __align__(16) char smem[];
    const uint32_t sb = smem_u32(smem);

    const int b   = blockIdx.y;
    const int t0  = blockIdx.x * TN_;
    const int tid = threadIdx.x;
    const int lane = tid & 31;
    const bool is_producer = (tid >= 256);

    const float* xb = x + (size_t)b * C_ * T_;
    const char* xrow_base = (const char*)(xb) + (size_t)t0 * 4;
    const __half* gw = g_w + (size_t)b * M_ * CP_;

    // ---------------- producer helpers ----------------
    const int ptid = tid - 256;        // 0..127
    const int ph   = ptid >> 6;        // k half 0/1
    const int tcol = ptid & 63;        // t column 0..63

    auto issue_chunk = [&](int chunk) {
        const int k0 = chunk * KC_;
        const int s  = chunk % NSTAGE;
        // A tile: 128 rows x 64B = 512 x 16B chunks, 4 per thread
#pragma unroll
        for (int r = 0; r < 4; r++) {
            const int c = ptid + r * 128;
            const int row = c >> 2, j = c & 3;
            const __half* src = gw + (size_t)row * CP_ + k0 + j * 8;
            CP16(sb + OFF_A(s) + row * RS + j * 16, src, 16);
        }
        // X staging: 32 k-rows x 256B = 512 x 16B chunks, 4 per thread
#pragma unroll
        for (int r = 0; r < 4; r++) {
            const int c = ptid + r * 128;
            const int k = c >> 4;
            const int j = c & 15;
            const char* src = xrow_base + (size_t)(k0 + k) * (T_ * 4) + j * 16;
            const uint32_t dst = sb + OFF_X(s) + k * RSX + j * 16;
            const uint32_t sz = ((k0 + k) < C_ && (t0 + j * 4) < T_) ? 16u : 0u;
            CP16(dst, src, sz);
        }
        CP_COMMIT();
    };

    // Thread (ph, tcol): convert 16 k-values of column tcol into B row tcol.
    auto convert_chunk = [&](int chunk) {
        const int k0 = chunk * KC_;
        const int s  = chunk % NSTAGE;
        const uint32_t xbase = sb + OFF_X(s) + ph * (16 * RSX) + tcol * 4;
        float v[16];
#pragma unroll
        for (int j = 0; j < 16; j++) {
            float f;
            asm volatile("ld.shared.f32 %0, [%1];" : "=f"(f) : "r"(xbase + j * RSX));
            v[j] = ((k0 + ph * 16 + j) < C_) ? f : 0.0f;   // kill K-padding garbage
        }
        uint32_t hp[8];
#pragma unroll
        for (int q = 0; q < 8; q++) {
            __half h0 = __float2half(v[2 * q]);
            __half h1 = __float2half(v[2 * q + 1]);
            hp[q] = (uint32_t)__half_as_ushort(h0)
                  | ((uint32_t)__half_as_ushort(h1) << 16);
        }
        const uint32_t bbase = sb + OFF_B(s) + tcol * RS + ph * 32;
        uint4 v0 = make_uint4(hp[0], hp[1], hp[2], hp[3]);
        uint4 v1 = make_uint4(hp[4], hp[5], hp[6], hp[7]);
        STS16(bbase,      v0);
        STS16(bbase + 16, v1);
    };

    // ---------------- consumer setup ----------------
    const int wid = tid >> 5;
    const int warp_m = wid >> 1;        // 0..3
    const int warp_n = wid & 1;         // 0..1

    const int lr  = lane & 7;
    const int sel = lane >> 3;          // 0..3
    const int a_row = warp_m * 32 + lr + (sel & 1) * 8;
    const int a_col = (sel >> 1) * 16;
    const int b_row = warp_n * 32 + lr + (sel >> 1) * 8;
    const int b_col = (sel & 1) * 16;

    float acc[2][4][4];
#pragma unroll
    for (int i = 0; i < 2; i++)
#pragma unroll
        for (int j = 0; j < 4; j++)
#pragma unroll
            for (int q = 0; q < 4; q++) acc[i][j][q] = 0.0f;

    // ---------------- prologue: chunks 0..2 in flight, chunk 0 converted ----
    if (is_producer) {
        issue_chunk(0);
        issue_chunk(1);
        issue_chunk(2);
        asm volatile("cp.async.wait_group 2;" ::: "memory");   // chunk 0 arrived
        PROD_BAR();                 // all producers' chunk-0 groups retired
        convert_chunk(0);
    }
    __syncthreads();

    // ---------------- main loop (one block barrier per iter) ----------------
    for (int i = 0; i < NCHUNK; i++) {
        if (is_producer) {
            if (i + 3 < NCHUNK) issue_chunk(i + 3);
            if (i + 1 < NCHUNK) {
                // retire chunk i+1's group (outstanding after issue: i+1..min(i+3,N-1))
                if (i + 3 < NCHUNK)      asm volatile("cp.async.wait_group 2;" ::: "memory");
                else if (i + 2 < NCHUNK) asm volatile("cp.async.wait_group 1;" ::: "memory");
                else                     asm volatile("cp.async.wait_group 0;" ::: "memory");
                PROD_BAR();         // cross-thread cp.async visibility
                convert_chunk(i + 1);
            }
        } else {
            const uint32_t sA = sb + OFF_A(i % NSTAGE);
            const uint32_t sB = sb + OFF_B(i % NSTAGE);
#pragma unroll
            for (int ks = 0; ks < 2; ks++) {
                uint32_t af[2][4], bf[2][4];
                const uint32_t acol = ks * 32 + a_col;
                const uint32_t bcol = ks * 32 + b_col;
#pragma unroll
                for (int g = 0; g < 2; g++)
                    LDSM4(bf[g], sB + (uint32_t)(b_row + g * 16) * RS + bcol);
#pragma unroll
                for (int mf = 0; mf < 2; mf++)
                    LDSM4(af[mf], sA + (uint32_t)(a_row + mf * 16) * RS + acol);
#pragma unroll
                for (int mf = 0; mf < 2; mf++)
#pragma unroll
                    for (int nf = 0; nf < 4; nf++) {
                        const int g = nf >> 1, s2 = (nf & 1) * 2;
                        MMA_F16(acc[mf][nf], af[mf], bf[g][s2], bf[g][s2 + 1]);
                    }
            }
        }
        __syncthreads();
    }

    // ---------------- epilogue (consumers only) ----------------
    if (!is_producer && (t0 + warp_n * 32 < T_)) {
        const int mb = warp_m * 32 + (lane >> 2);
        const int cb = t0 + warp_n * 32 + (lane & 3) * 2;
#pragma unroll
        for (int mf = 0; mf < 2; mf++) {
#pragma unroll
            for (int nf = 0; nf < 4; nf++) {
                const int m = mb + mf * 16;
                const int t = cb + nf * 8;
                float* o0 = out + ((size_t)b * M_ + m) * T_ + t;
                float* o1 = out + ((size_t)b * M_ + m + 8) * T_ + t;
                *(float2*)o0 = make_float2(acc[mf][nf][0], acc[mf][nf][1]);
                *(float2*)o1 = make_float2(acc[mf][nf][2], acc[mf][nf][3]);
            }
        }
    }
}

// ---------------------------------------------------------------------------
extern "C" void kernel_launch(void* const* d_in, const int* in_sizes, int n_in,
                              void* d_out, int out_size) {
    const float* x    = (const float*)d_in[0];
    const float* pos  = (const float*)d_in[1];
    const float* tpos = (const float*)d_in[2];
    const float* w1   = (const float*)d_in[3];
    const float* b1   = (const float*)d_in[4];
    const float* w2   = (const float*)d_in[5];
    const float* b2   = (const float*)d_in[6];
    float* out = (float*)d_out;

    cudaFuncSetAttribute(mrm_hmma_kernel,
                         cudaFuncAttributeMaxDynamicSharedMemorySize, SMEM_TOTAL);

    mrm_weights_kernel<<<B_ * M_, CP_>>>(pos, tpos, w1, b1, w2, b2);

    dim3 grid(NTT, B_);   // 63 x 16 = 1008 CTAs
    mrm_hmma_kernel<<<grid, NTHREADS, SMEM_TOTAL>>>(x, out);
}

// round 16
// speedup vs baseline: 1.1163x; 1.0040x over previous
#include <cuda_runtime.h>
#include <cuda_fp16.h>
#include <cstdint>

// ---------------------------------------------------------------------------
// Problem constants
// ---------------------------------------------------------------------------
#define B_   16
#define C_   306
#define CP_  320      // C padded to multiple of 32
#define T_   4000
#define M_   128
#define TN_  64       // t-tile per CTA
#define KC_  32       // K chunk
#define NCHUNK 10     // CP_/KC_
#define NTT  63       // ceil(T_/TN_)
#define NSTAGE 4      // pipeline stages (prefetch distance 3)

#define INV0 50.0f
#define INV1 12.5f
#define INV2 3.125f

// smem row strides (data + 16B pad -> conflict-free ldmatrix)
#define RS   80       // A rows and B rows (64B fp16 data)
#define RSX  272      // X staging rows (256B fp32 data)

// SMEM layout (bytes, dynamic) — 4 uniform stages
#define OFF_A(s)  ((s) * 10240)            // 4 stages: 128 rows x 80
#define OFF_X(s)  (40960 + (s) * 8704)     // 4 stages: 32 rows x 272
#define OFF_B(s)  (75776 + (s) * 5120)     // 4 stages: 64 rows x 80
#define SMEM_TOTAL 96256

#define NTHREADS 384   // 8 consumer warps + 4 producer warps

// Scratch: normalized channel weights, fp16, layout [b][m][c] (padded)
__device__ __align__(16) __half g_w[B_ * M_ * CP_];

__device__ __forceinline__ uint32_t smem_u32(const void* p) {
    uint32_t a;
    asm("{ .reg .u64 t; cvta.to.shared.u64 t, %1; cvt.u32.u64 %0, t; }" : "=r"(a) : "l"(p));
    return a;
}

#define LDSM4(r, addr) \
    asm volatile("ldmatrix.sync.aligned.m8n8.x4.shared.b16 {%0,%1,%2,%3}, [%4];" \
        : "=r"((r)[0]), "=r"((r)[1]), "=r"((r)[2]), "=r"((r)[3]) : "r"(addr))

#define STS16(addr, v) \
    asm volatile("st.shared.v4.b32 [%0], {%1,%2,%3,%4};" \
        :: "r"(addr), "r"((v).x), "r"((v).y), "r"((v).z), "r"((v).w) : "memory")

#define CP16(dst, src, sz) \
    asm volatile("cp.async.cg.shared.global [%0], [%1], 16, %2;" \
        :: "r"(dst), "l"(src), "r"(sz) : "memory")

#define CP_COMMIT() asm volatile("cp.async.commit_group;" ::: "memory")

// Producer-only barrier (cross-thread cp.async visibility before convert).
#define PROD_BAR() asm volatile("bar.sync 1, 128;" ::: "memory")

#define MMA_F16(c, a, b0, b1) \
    asm volatile("mma.sync.aligned.m16n8k16.row.col.f32.f16.f16.f32 " \
        "{%0,%1,%2,%3}, {%4,%5,%6,%7}, {%8,%9}, {%0,%1,%2,%3};" \
        : "+f"((c)[0]), "+f"((c)[1]), "+f"((c)[2]), "+f"((c)[3]) \
        : "r"((a)[0]), "r"((a)[1]), "r"((a)[2]), "r"((a)[3]), "r"(b0), "r"(b1))

// ---------------------------------------------------------------------------
// Kernel 1: gate weights (one (b,m) per block).
// ---------------------------------------------------------------------------
__global__ void __launch_bounds__(CP_) mrm_weights_kernel(
    const float* __restrict__ pos, const float* __restrict__ tpos,
    const float* __restrict__ w1, const float* __restrict__ b1,
    const float* __restrict__ w2, const float* __restrict__ b2)
{
    __shared__ float s_w1[96], s_b1[32], s_w2[32];
    __shared__ float warp_sums[10];
    __shared__ float s_total;

    const int bm = blockIdx.x;
    const int b = bm / M_, m = bm % M_;
    const int tid = threadIdx.x;

    if (tid < 96) s_w1[tid] = w1[tid];
    else if (tid < 128) s_b1[tid - 96] = b1[tid - 96];
    else if (tid < 160) s_w2[tid - 128] = w2[tid - 128];
    __syncthreads();

    const float txp = tpos[2 * m], typ = tpos[2 * m + 1];
    const float bias2 = b2[0];

    float wv = 0.0f;
    const int c = tid;
    if (c < C_) {
        const float px = pos[((size_t)b * C_ + c) * 2 + 0];
        const float py = pos[((size_t)b * C_ + c) * 2 + 1];
        const float dx = px - txp, dy = py - typ;
        const float d2 = dx * dx + dy * dy;
        const float s0 = __expf(-d2 * INV0);
        const float s1 = __expf(-d2 * INV1);
        const float s2 = __expf(-d2 * INV2);
        float acc = bias2;
#pragma unroll
        for (int j = 0; j < 32; j++) {
            float h = s_b1[j];
            h = fmaf(s0, s_w1[j], h);
            h = fmaf(s1, s_w1[32 + j], h);
            h = fmaf(s2, s_w1[64 + j], h);
            h = fmaxf(h, 0.0f);
            acc = fmaf(h, s_w2[j], acc);
        }
        wv = acc;
    }

    float v = wv;
#pragma unroll
    for (int o = 16; o > 0; o >>= 1) v += __shfl_down_sync(0xffffffffu, v, o);
    if ((tid & 31) == 0) warp_sums[tid >> 5] = v;
    __syncthreads();
    if (tid == 0) {
        float s = 0.0f;
#pragma unroll
        for (int i = 0; i < 10; i++) s += warp_sums[i];
        s_total = s + 1e-8f;
    }
    __syncthreads();

    const float wn = (c < C_) ? (wv / s_total) : 0.0f;   // padding rows get 0
    g_w[((size_t)b * M_ + m) * CP_ + c] = __float2half(wn);

#if __CUDA_ARCH__ >= 900
    cudaTriggerProgrammaticLaunchCompletion();
#endif
}

// ---------------------------------------------------------------------------
// Kernel 2: warp-specialized fp16 HMMA GEMM, CTA tile 128x64, 4-stage
// cp.async pipeline (prefetch distance 3). PDL: X prefetch overlaps the
// weights kernel; producers grid-sync before touching g_w.
// ---------------------------------------------------------------------------
__global__ void __launch_bounds__(NTHREADS, 2) mrm_hmma_kernel(
    const float* __restrict__ x, float* __restrict__ out)
{
    extern __shared__ __align__(16) char smem[];
    const uint32_t sb = smem_u32(smem);

    const int b   = blockIdx.y;
    const int t0  = blockIdx.x * TN_;
    const int tid = threadIdx.x;
    const int lane = tid & 31;
    const bool is_producer = (tid >= 256);

    const float* xb = x + (size_t)b * C_ * T_;
    const char* xrow_base = (const char*)(xb) + (size_t)t0 * 4;
    const __half* gw = g_w + (size_t)b * M_ * CP_;

    // ---------------- producer helpers ----------------
    const int ptid = tid - 256;        // 0..127
    const int ph   = ptid >> 6;        // k half 0/1
    const int tcol = ptid & 63;        // t column 0..63

    auto issue_A = [&](int chunk) {
        const int k0 = chunk * KC_;
        const int s  = chunk % NSTAGE;
#pragma unroll
        for (int r = 0; r < 4; r++) {
            const int c = ptid + r * 128;
            const int row = c >> 2, j = c & 3;
            const __half* src = gw + (size_t)row * CP_ + k0 + j * 8;
            CP16(sb + OFF_A(s) + row * RS + j * 16, src, 16);
        }
    };

    auto issue_X = [&](int chunk) {
        const int k0 = chunk * KC_;
        const int s  = chunk % NSTAGE;
#pragma unroll
        for (int r = 0; r < 4; r++) {
            const int c = ptid + r * 128;
            const int k = c >> 4;
            const int j = c & 15;
            const char* src = xrow_base + (size_t)(k0 + k) * (T_ * 4) + j * 16;
            const uint32_t dst = sb + OFF_X(s) + k * RSX + j * 16;
            const uint32_t sz = ((k0 + k) < C_ && (t0 + j * 4) < T_) ? 16u : 0u;
            CP16(dst, src, sz);
        }
    };

    // Thread (ph, tcol): convert 16 k-values of column tcol into B row tcol.
    auto convert_chunk = [&](int chunk) {
        const int k0 = chunk * KC_;
        const int s  = chunk % NSTAGE;
        const uint32_t xbase = sb + OFF_X(s) + ph * (16 * RSX) + tcol * 4;
        float v[16];
#pragma unroll
        for (int j = 0; j < 16; j++) {
            float f;
            asm volatile("ld.shared.f32 %0, [%1];" : "=f"(f) : "r"(xbase + j * RSX));
            v[j] = ((k0 + ph * 16 + j) < C_) ? f : 0.0f;   // kill K-padding garbage
        }
        uint32_t hp[8];
#pragma unroll
        for (int q = 0; q < 8; q++) {
            __half h0 = __float2half(v[2 * q]);
            __half h1 = __float2half(v[2 * q + 1]);
            hp[q] = (uint32_t)__half_as_ushort(h0)
                  | ((uint32_t)__half_as_ushort(h1) << 16);
        }
        const uint32_t bbase = sb + OFF_B(s) + tcol * RS + ph * 32;
        uint4 v0 = make_uint4(hp[0], hp[1], hp[2], hp[3]);
        uint4 v1 = make_uint4(hp[4], hp[5], hp[6], hp[7]);
        STS16(bbase,      v0);
        STS16(bbase + 16, v1);
    };

    // ---------------- consumer setup ----------------
    const int wid = tid >> 5;
    const int warp_m = wid >> 1;        // 0..3
    const int warp_n = wid & 1;         // 0..1

    const int lr  = lane & 7;
    const int sel = lane >> 3;          // 0..3
    const int a_row = warp_m * 32 + lr + (sel & 1) * 8;
    const int a_col = (sel >> 1) * 16;
    const int b_row = warp_n * 32 + lr + (sel >> 1) * 8;
    const int b_col = (sel & 1) * 16;

    float acc[2][4][4];
#pragma unroll
    for (int i = 0; i < 2; i++)
#pragma unroll
        for (int j = 0; j < 4; j++)
#pragma unroll
            for (int q = 0; q < 4; q++) acc[i][j][q] = 0.0f;

    // ---------------- prologue ----------------
    // Groups: {X0,X1,X2}, then (after grid sync) {A0}, {A1}, {A2}.
    // wait_group 2 retires {X012}+{A0} == chunk 0 complete; {A1},{A2} remain
    // outstanding — identical steady-state accounting to the 1-group-per-chunk
    // scheme (chunks 1,2 outstanding).
    if (is_producer) {
        issue_X(0); issue_X(1); issue_X(2);
        CP_COMMIT();                       // group {X0,X1,X2}
#if __CUDA_ARCH__ >= 900
        cudaGridDependencySynchronize();   // g_w ready (no-op w/o PDL)
#endif
        issue_A(0); CP_COMMIT();           // group {A0}
        issue_A(1); CP_COMMIT();           // group {A1}
        issue_A(2); CP_COMMIT();           // group {A2}
        asm volatile("cp.async.wait_group 2;" ::: "memory");   // chunk 0 resident
        PROD_BAR();                 // all producers' chunk-0 data visible
        convert_chunk(0);
    }
    __syncthreads();

    // ---------------- main loop (one block barrier per iter) ----------------
    for (int i = 0; i < NCHUNK; i++) {
        if (is_producer) {
            if (i + 3 < NCHUNK) { issue_A(i + 3); issue_X(i + 3); CP_COMMIT(); }
            if (i + 1 < NCHUNK) {
                if (i + 3 < NCHUNK)      asm volatile("cp.async.wait_group 2;" ::: "memory");
                else if (i + 2 < NCHUNK) asm volatile("cp.async.wait_group 1;" ::: "memory");
                else                     asm volatile("cp.async.wait_group 0;" ::: "memory");
                PROD_BAR();         // cross-thread cp.async visibility
                convert_chunk(i + 1);
            }
        } else {
            const uint32_t sA = sb + OFF_A(i % NSTAGE);
            const uint32_t sB = sb + OFF_B(i % NSTAGE);
#pragma unroll
            for (int ks = 0; ks < 2; ks++) {
                uint32_t af[2][4], bf[2][4];
                const uint32_t acol = ks * 32 + a_col;
                const uint32_t bcol = ks * 32 + b_col;
#pragma unroll
                for (int g = 0; g < 2; g++)
                    LDSM4(bf[g], sB + (uint32_t)(b_row + g * 16) * RS + bcol);
#pragma unroll
                for (int mf = 0; mf < 2; mf++)
                    LDSM4(af[mf], sA + (uint32_t)(a_row + mf * 16) * RS + acol);
#pragma unroll
                for (int mf = 0; mf < 2; mf++)
#pragma unroll
                    for (int nf = 0; nf < 4; nf++) {
                        const int g = nf >> 1, s2 = (nf & 1) * 2;
                        MMA_F16(acc[mf][nf], af[mf], bf[g][s2], bf[g][s2 + 1]);
                    }
            }
        }
        __syncthreads();
    }

    // ---------------- epilogue (consumers only) ----------------
    if (!is_producer && (t0 + warp_n * 32 < T_)) {
        const int mb = warp_m * 32 + (lane >> 2);
        const int cb = t0 + warp_n * 32 + (lane & 3) * 2;
#pragma unroll
        for (int mf = 0; mf < 2; mf++) {
#pragma unroll
            for (int nf = 0; nf < 4; nf++) {
                const int m = mb + mf * 16;
                const int t = cb + nf * 8;
                float* o0 = out + ((size_t)b * M_ + m) * T_ + t;
                float* o1 = out + ((size_t)b * M_ + m + 8) * T_ + t;
                *(float2*)o0 = make_float2(acc[mf][nf][0], acc[mf][nf][1]);
                *(float2*)o1 = make_float2(acc[mf][nf][2], acc[mf][nf][3]);
            }
        }
    }
}

// ---------------------------------------------------------------------------
extern "C" void kernel_launch(void* const* d_in, const int* in_sizes, int n_in,
                              void* d_out, int out_size) {
    const float* x    = (const float*)d_in[0];
    const float* pos  = (const float*)d_in[1];
    const float* tpos = (const float*)d_in[2];
    const float* w1   = (const float*)d_in[3];
    const float* b1   = (const float*)d_in[4];
    const float* w2   = (const float*)d_in[5];
    const float* b2   = (const float*)d_in[6];
    float* out = (float*)d_out;

    cudaFuncSetAttribute(mrm_hmma_kernel,
                         cudaFuncAttributeMaxDynamicSharedMemorySize, SMEM_TOTAL);

    mrm_weights_kernel<<<B_ * M_, CP_>>>(pos, tpos, w1, b1, w2, b2);

    // GEMM with programmatic dependent launch (falls back to plain launch).
    cudaLaunchConfig_t cfg = {};
    cfg.gridDim = dim3(NTT, B_);
    cfg.blockDim = dim3(NTHREADS, 1, 1);
    cfg.dynamicSmemBytes = SMEM_TOTAL;
    cfg.stream = 0;
    cudaLaunchAttribute attrs[1];
    attrs[0].id = cudaLaunchAttributeProgrammaticStreamSerialization;
    attrs[0].val.programmaticStreamSerializationAllowed = 1;
    cfg.attrs = attrs;
    cfg.numAttrs = 1;
    cudaError_t err = cudaLaunchKernelEx(&cfg, mrm_hmma_kernel, x, out);
    if (err != cudaSuccess) {
        dim3 grid(NTT, B_);
        mrm_hmma_kernel<<<grid, NTHREADS, SMEM_TOTAL>>>(x, out);
    }
}